// round 9
// baseline (speedup 1.0000x reference)
#include <cuda_runtime.h>
#include <math_constants.h>

// x [B=64, C=512, H=28, W=28] fp32; cc [B,28,28] bool widened to int32.
// out [B, 2C]: out[b,c]   = (sum_hw x[b,c,hw]*cc[b,hw] + x[b,c,0]) / max(cnt_b,1)
//              out[b,C+c] = max_hw x[b,c,hw]
//
// Persistent software-pipelined warps, NO barriers: 592 CTAs x 8 warps = 4736
// independent warps, each streams ~7 rows. Double-buffered register pipeline:
// row i+1's 7 float4 LDGs are in flight while row i is consumed/reduced/written,
// so DRAM load issue never pauses (fixes the 62% wave-burst ceiling).

#define HW        784
#define C_DIM     512
#define THREADS   256
#define N_ROWS    32768                       // 64*512
#define GRID      592                         // 148 SMs * 4
#define WT        (GRID * (THREADS / 32))     // 4736 total warps

__device__ __forceinline__ void load_row(const float* __restrict__ x,
                                         int bc, int lane, float4 v[7])
{
    const float4* __restrict__ xr =
        reinterpret_cast<const float4*>(x + (size_t)bc * HW);
    #pragma unroll
    for (int j = 0; j < 6; j++) v[j] = xr[lane + 32 * j];
    if (lane < 4) v[6] = xr[lane + 192];
}

__device__ __forceinline__ void consume_row(const int* __restrict__ cc,
                                            int bc, int lane,
                                            const float4 v[7],
                                            float* __restrict__ out)
{
    const int b = bc >> 9;
    const int4* __restrict__ mr =
        reinterpret_cast<const int4*>(cc + (size_t)b * HW);

    float sum0 = 0.0f, sum1 = 0.0f;
    int   icnt = 0;
    float mx   = -CUDART_INF_F;

    #pragma unroll
    for (int j = 0; j < 6; j++) {
        int4 m = mr[lane + 32 * j];
        sum0 += (m.x ? v[j].x : 0.0f) + (m.y ? v[j].y : 0.0f);
        sum1 += (m.z ? v[j].z : 0.0f) + (m.w ? v[j].w : 0.0f);
        icnt += (m.x != 0) + (m.y != 0) + (m.z != 0) + (m.w != 0);
        mx = fmaxf(mx, fmaxf(fmaxf(v[j].x, v[j].y), fmaxf(v[j].z, v[j].w)));
    }
    if (lane < 4) {
        int4 m = mr[lane + 192];
        sum0 += (m.x ? v[6].x : 0.0f) + (m.y ? v[6].y : 0.0f);
        sum1 += (m.z ? v[6].z : 0.0f) + (m.w ? v[6].w : 0.0f);
        icnt += (m.x != 0) + (m.y != 0) + (m.z != 0) + (m.w != 0);
        mx = fmaxf(mx, fmaxf(fmaxf(v[6].x, v[6].y), fmaxf(v[6].z, v[6].w)));
    }

    float sum = sum0 + sum1;
    #pragma unroll
    for (int off = 16; off > 0; off >>= 1) {
        sum  += __shfl_down_sync(0xffffffffu, sum, off);
        icnt += __shfl_down_sync(0xffffffffu, icnt, off);
        mx    = fmaxf(mx, __shfl_down_sync(0xffffffffu, mx, off));
    }

    if (lane == 0) {
        const int c = bc & (C_DIM - 1);
        sum += v[0].x;                         // + x[b,c,0,0] quirk (lane0 v[0].x)
        float denom = (icnt == 0) ? 1.0f : (float)icnt;
        out[(size_t)b * (2 * C_DIM) + c]         = sum / denom;
        out[(size_t)b * (2 * C_DIM) + C_DIM + c] = mx;
    }
}

__global__ __launch_bounds__(THREADS) void pool_kernel(
    const float* __restrict__ x,
    const int* __restrict__ cc,
    float* __restrict__ out)
{
    const int lane = threadIdx.x & 31;
    const int gw   = blockIdx.x * (THREADS / 32) + (threadIdx.x >> 5);

    float4 va[7], vb[7];

    int r = gw;
    if (r >= N_ROWS) return;

    load_row(x, r, lane, va);

    while (true) {
        int r2 = r + WT;
        if (r2 < N_ROWS) {
            load_row(x, r2, lane, vb);        // next row in flight
            consume_row(cc, r, lane, va, out);
            int r3 = r2 + WT;
            if (r3 < N_ROWS) {
                load_row(x, r3, lane, va);    // next-next in flight
                consume_row(cc, r2, lane, vb, out);
                r = r3;
            } else {
                consume_row(cc, r2, lane, vb, out);
                break;
            }
        } else {
            consume_row(cc, r, lane, va, out);
            break;
        }
    }
}

extern "C" void kernel_launch(void* const* d_in, const int* in_sizes, int n_in,
                              void* d_out, int out_size)
{
    const float* x  = (const float*)d_in[0];
    const int*   cc = (const int*)d_in[1];
    float*       o  = (float*)d_out;

    pool_kernel<<<GRID, THREADS>>>(x, cc, o);
}